// round 7
// baseline (speedup 1.0000x reference)
#include <cuda_runtime.h>
#include <cstdint>

#define SEQ   256
#define BATCH 8192

// pack two f32 -> f16x2 (lo = first arg)
__device__ __forceinline__ uint32_t pkh(float lo, float hi) {
    uint32_t u; asm("cvt.rn.f16x2.f32 %0, %2, %1;" : "=r"(u) : "f"(lo), "f"(hi)); return u;
}
__device__ __forceinline__ void mma16(float d[4], const uint32_t a[4], uint32_t b0, uint32_t b1) {
    asm("mma.sync.aligned.m16n8k16.row.col.f32.f16.f16.f32 "
        "{%0,%1,%2,%3},{%4,%5,%6,%7},{%8,%9},{%0,%1,%2,%3};"
        : "+f"(d[0]), "+f"(d[1]), "+f"(d[2]), "+f"(d[3])
        : "r"(a[0]), "r"(a[1]), "r"(a[2]), "r"(a[3]), "r"(b0), "r"(b1));
}
__device__ __forceinline__ float sig_t(float x) {
    float t; asm("tanh.approx.f32 %0, %1;" : "=f"(t) : "f"(0.5f * x));
    return fmaf(t, 0.5f, 0.5f);
}
__device__ __forceinline__ float tanh_ap(float x) {
    float t; asm("tanh.approx.f32 %0, %1;" : "=f"(t) : "f"(x)); return t;
}

// Grid: 148 blocks x 128 threads (4 warps = 2 pairs).
// Pair-unit P = (wid>>1)*148 + bid, active iff P < 256; pair owns 32 rows
// [32P, 32P+32) as two m16 row-groups. Warp s = wid&1 owns columns [16s,16s+16).
// Lane: g = lane>>2 (rows m*16+g, m*16+g+8), tg = lane&3.
__global__ void __launch_bounds__(128, 1) gru2_hmma32_kernel(
    const float* __restrict__ x,
    const float* __restrict__ h_in,
    const float* __restrict__ Wih0,
    const float* __restrict__ Whh0,
    const float* __restrict__ bih0,
    const float* __restrict__ bhh0,
    const float* __restrict__ Wih1,
    const float* __restrict__ Whh1,
    const float* __restrict__ bih1,
    const float* __restrict__ bhh1,
    const float* __restrict__ Wout,
    const float* __restrict__ bout,
    float* __restrict__ out)
{
    // fp16 B-fragment table: per half s, 18 uint4-slots x 32 lanes.
    //  slot 0..5  : L0 Whh0, rows (slot>>1)*32 + 16s + (slot&1)*8
    //  slot 6..13 : L1 r/z (q=slot-6, nt=q>>1; q even->Wih1, odd->Whh1)
    //  slot 14,15 : L1 i_n (Wih1 rows 64+16s+8i)
    //  slot 16,17 : L1 h_n (Whh1 rows 64+16s+8i)
    __shared__ __align__(16) uint4  BW[36 * 32];      // 18432 B
    __shared__ float4 cA4s[32];                        // (WihR,WihZ,WihN,bin0)
    __shared__ float4 cB0s[32];                        // (br0c,bz0c,bhn0,Wout)
    __shared__ float4 cB1s[32];                        // (br1c,bz1c,bin1,bhn1)
    __shared__ uint32_t hs0[2 * 32 * 20];              // f16x2 h0, 2 pairs x 32 rows
    __shared__ uint32_t hs1[2 * 32 * 20];              // f16x2 h1
    __shared__ float  yS[2 * 64];
    __shared__ float  boS;

    const int tid = threadIdx.x;

    for (int idx = tid; idx < 36 * 32; idx += 128) {
        int blkid = idx >> 5, l = idx & 31, gg = l >> 2, tt = l & 3;
        int sH = blkid >= 18, slot = blkid - sH * 18;
        const float* src; int rowb;
        if (slot < 6) {
            src = Whh0; rowb = (slot >> 1) * 32 + sH * 16 + (slot & 1) * 8;
        } else if (slot < 14) {
            int q = slot - 6, nt = q >> 1;
            src = (q & 1) ? Whh1 : Wih1;
            rowb = (nt >> 1) * 32 + sH * 16 + (nt & 1) * 8;
        } else if (slot < 16) {
            src = Wih1; rowb = 64 + sH * 16 + (slot - 14) * 8;
        } else {
            src = Whh1; rowb = 64 + sH * 16 + (slot - 16) * 8;
        }
        const float* wr = src + (rowb + gg) * 32 + 2 * tt;
        BW[idx] = make_uint4(pkh(wr[0],  wr[1]),  pkh(wr[8],  wr[9]),
                             pkh(wr[16], wr[17]), pkh(wr[24], wr[25]));
    }
    if (tid < 32) {
        int j = tid;
        cA4s[j] = make_float4(Wih0[j], Wih0[32 + j], Wih0[64 + j], bih0[64 + j]);
        cB0s[j] = make_float4(bih0[j] + bhh0[j], bih0[32 + j] + bhh0[32 + j],
                              bhh0[64 + j], Wout[j]);
        cB1s[j] = make_float4(bih1[j] + bhh1[j], bih1[32 + j] + bhh1[32 + j],
                              bih1[64 + j], bhh1[64 + j]);
    }
    if (tid == 0) boS = bout[0];
    __syncthreads();

    const int wid  = tid >> 5;
    const int lane = tid & 31;
    const int pib  = wid >> 1;
    const int s    = wid & 1;
    const int P    = pib * 148 + blockIdx.x;
    if (P >= 256) return;

    const int g  = lane >> 2;
    const int tg = lane & 3;
    const int base = P * 32;
    const int barId = 1 + pib;
    const int colb = s * 16;
    uint32_t* hx0 = hs0 + pib * 640;
    uint32_t* hx1 = hs1 + pib * 640;
    float* yP = yS + pib * 64;
    const uint4* BWs = BW + s * 18 * 32;
    const float bo = boS;

#define BARP() asm volatile("bar.sync %0, 64;" :: "r"(barId) : "memory")

    // Wout for owned columns (4 regs)
    float wo[4];
#pragma unroll
    for (int i = 0; i < 2; i++)
#pragma unroll
        for (int c = 0; c < 2; c++) wo[i * 2 + c] = cB0s[colb + i * 8 + 2 * tg + c].w;

    // h in D-layout (fp32): [m][i*4 + rr*2 + c]
    float h0D[2][8], h1D[2][8];
#pragma unroll
    for (int m = 0; m < 2; m++)
#pragma unroll
        for (int i = 0; i < 2; i++)
#pragma unroll
            for (int rr = 0; rr < 2; rr++) {
                size_t r0 = (size_t)(base + m * 16 + g + 8 * rr) * 32 + colb + i * 8 + 2 * tg;
                float2 v0 = *(const float2*)&h_in[r0];
                float2 v1 = *(const float2*)&h_in[(size_t)BATCH * 32 + r0];
                h0D[m][i * 4 + rr * 2] = v0.x; h0D[m][i * 4 + rr * 2 + 1] = v0.y;
                h1D[m][i * 4 + rr * 2] = v1.x; h1D[m][i * 4 + rr * 2 + 1] = v1.y;
            }

    uint32_t h0A[2][8], h1A[2][8];   // fp16 A fragments per row-group

#define STORE_H(hD, hx, m)                                                       \
    do {                                                                         \
        _Pragma("unroll")                                                        \
        for (int i = 0; i < 2; i++)                                              \
            _Pragma("unroll")                                                    \
            for (int rr = 0; rr < 2; rr++)                                       \
                hx[((m) * 16 + g + 8 * rr) * 20 + 8 * s + 4 * i + tg] =          \
                    pkh(hD[i * 4 + rr * 2], hD[i * 4 + rr * 2 + 1]);             \
    } while (0)

#define LOAD_A(hx, hA, m)                                                        \
    do {                                                                         \
        _Pragma("unroll")                                                        \
        for (int kp = 0; kp < 2; kp++) {                                         \
            hA[kp * 4 + 0] = hx[((m) * 16 + g) * 20 + tg + 8 * kp];              \
            hA[kp * 4 + 1] = hx[((m) * 16 + g + 8) * 20 + tg + 8 * kp];          \
            hA[kp * 4 + 2] = hx[((m) * 16 + g) * 20 + tg + 4 + 8 * kp];          \
            hA[kp * 4 + 3] = hx[((m) * 16 + g + 8) * 20 + tg + 4 + 8 * kp];      \
        }                                                                        \
    } while (0)

#pragma unroll
    for (int m = 0; m < 2; m++) { STORE_H(h0D[m], hx0, m); STORE_H(h1D[m], hx1, m); }
    BARP();
#pragma unroll
    for (int m = 0; m < 2; m++) { LOAD_A(hx0, h0A[m], m); LOAD_A(hx1, h1A[m], m); }

    float xc[2][2], xn[2][2];
#pragma unroll
    for (int m = 0; m < 2; m++) {
        xc[m][0] = __ldg(x + base + m * 16 + g);
        xc[m][1] = __ldg(x + base + m * 16 + g + 8);
    }

    for (int st = 0; st < SEQ; st++) {
        const size_t nxt = (size_t)min(st + 1, SEQ - 1) * BATCH;
#pragma unroll
        for (int m = 0; m < 2; m++) {
            xn[m][0] = __ldg(x + nxt + base + m * 16 + g);
            xn[m][1] = __ldg(x + nxt + base + m * 16 + g + 8);
        }

        // ---------- layer 0: 6 B-loads, 24 MMAs (B reused across 2 groups) ----------
        float D0[2][6][4];
#pragma unroll
        for (int m = 0; m < 2; m++)
#pragma unroll
            for (int q = 0; q < 6; q++)
#pragma unroll
                for (int v = 0; v < 4; v++) D0[m][q][v] = 0.0f;
#pragma unroll
        for (int nt = 0; nt < 6; nt++) {
            uint4 B = BWs[nt * 32 + lane];
#pragma unroll
            for (int m = 0; m < 2; m++) {
                mma16(D0[m][nt], h0A[m],     B.x, B.y);
                mma16(D0[m][nt], h0A[m] + 4, B.z, B.w);
            }
        }
#pragma unroll
        for (int i = 0; i < 2; i++)
#pragma unroll
            for (int c = 0; c < 2; c++) {
                const int j = colb + i * 8 + 2 * tg + c;
                const float4 A  = cA4s[j];
                const float4 Bc = cB0s[j];
#pragma unroll
                for (int m = 0; m < 2; m++)
#pragma unroll
                    for (int rr = 0; rr < 2; rr++) {
                        const float xv = xc[m][rr];
                        const int di = rr * 2 + c, hi = i * 4 + rr * 2 + c;
                        float r = sig_t(fmaf(xv, A.x, D0[m][i][di] + Bc.x));
                        float z = sig_t(fmaf(xv, A.y, D0[m][2 + i][di] + Bc.y));
                        float n = tanh_ap(fmaf(xv, A.z, A.w) + r * (D0[m][4 + i][di] + Bc.z));
                        float hold = h0D[m][hi];
                        h0D[m][hi] = n + z * (hold - n);
                    }
            }
#pragma unroll
        for (int m = 0; m < 2; m++) STORE_H(h0D[m], hx0, m);
        BARP();
#pragma unroll
        for (int m = 0; m < 2; m++) LOAD_A(hx0, h0A[m], m);

        // ---------- layer 1: 12 B-loads, 48 MMAs ----------
        float Drz[2][4][4], Din[2][2][4], Dhn[2][2][4];
#pragma unroll
        for (int m = 0; m < 2; m++) {
#pragma unroll
            for (int q = 0; q < 4; q++)
#pragma unroll
                for (int v = 0; v < 4; v++) Drz[m][q][v] = 0.0f;
#pragma unroll
            for (int q = 0; q < 2; q++)
#pragma unroll
                for (int v = 0; v < 4; v++) { Din[m][q][v] = 0.0f; Dhn[m][q][v] = 0.0f; }
        }
#pragma unroll
        for (int nt = 0; nt < 4; nt++) {
            uint4 Bi = BWs[(6 + nt * 2) * 32 + lane];
            uint4 Bh = BWs[(6 + nt * 2 + 1) * 32 + lane];
#pragma unroll
            for (int m = 0; m < 2; m++) {
                mma16(Drz[m][nt], h0A[m],     Bi.x, Bi.y);
                mma16(Drz[m][nt], h0A[m] + 4, Bi.z, Bi.w);
                mma16(Drz[m][nt], h1A[m],     Bh.x, Bh.y);
                mma16(Drz[m][nt], h1A[m] + 4, Bh.z, Bh.w);
            }
        }
#pragma unroll
        for (int i = 0; i < 2; i++) {
            uint4 B = BWs[(14 + i) * 32 + lane];
#pragma unroll
            for (int m = 0; m < 2; m++) {
                mma16(Din[m][i], h0A[m],     B.x, B.y);
                mma16(Din[m][i], h0A[m] + 4, B.z, B.w);
            }
        }
#pragma unroll
        for (int i = 0; i < 2; i++) {
            uint4 B = BWs[(16 + i) * 32 + lane];
#pragma unroll
            for (int m = 0; m < 2; m++) {
                mma16(Dhn[m][i], h1A[m],     B.x, B.y);
                mma16(Dhn[m][i], h1A[m] + 4, B.z, B.w);
            }
        }

        float y[2][2] = {{0.0f, 0.0f}, {0.0f, 0.0f}};
#pragma unroll
        for (int i = 0; i < 2; i++)
#pragma unroll
            for (int c = 0; c < 2; c++) {
                const float4 C = cB1s[colb + i * 8 + 2 * tg + c];
                const float w = wo[i * 2 + c];
#pragma unroll
                for (int m = 0; m < 2; m++)
#pragma unroll
                    for (int rr = 0; rr < 2; rr++) {
                        const int di = rr * 2 + c, hi = i * 4 + rr * 2 + c;
                        float r = sig_t(Drz[m][i][di] + C.x);
                        float z = sig_t(Drz[m][2 + i][di] + C.y);
                        float n = tanh_ap(Din[m][i][di] + C.z + r * (Dhn[m][i][di] + C.w));
                        float hold = h1D[m][hi];
                        float hn = n + z * (hold - n);
                        h1D[m][hi] = hn;
                        y[m][rr] = fmaf(hn, w, y[m][rr]);
                    }
            }
#pragma unroll
        for (int m = 0; m < 2; m++) STORE_H(h1D[m], hx1, m);
#pragma unroll
        for (int m = 0; m < 2; m++)
#pragma unroll
            for (int rr = 0; rr < 2; rr++) {
                y[m][rr] += __shfl_xor_sync(0xffffffffu, y[m][rr], 1);
                y[m][rr] += __shfl_xor_sync(0xffffffffu, y[m][rr], 2);
            }
        if (tg == 0) {
#pragma unroll
            for (int m = 0; m < 2; m++) {
                yP[m * 32 + s * 16 + g]     = y[m][0];
                yP[m * 32 + s * 16 + g + 8] = y[m][1];
            }
        }
        BARP();
#pragma unroll
        for (int m = 0; m < 2; m++) LOAD_A(hx1, h1A[m], m);
        if (s == 0 && tg == 0) {
#pragma unroll
            for (int m = 0; m < 2; m++) {
                out[(size_t)st * BATCH + base + m * 16 + g] =
                    yP[m * 32 + g] + yP[m * 32 + 16 + g] + bo;
                out[(size_t)st * BATCH + base + m * 16 + g + 8] =
                    yP[m * 32 + g + 8] + yP[m * 32 + 16 + g + 8] + bo;
            }
        }
#pragma unroll
        for (int m = 0; m < 2; m++) { xc[m][0] = xn[m][0]; xc[m][1] = xn[m][1]; }
    }

    // final h_state (2, B, 32)
    float* hout = out + (size_t)SEQ * BATCH;
#pragma unroll
    for (int m = 0; m < 2; m++)
#pragma unroll
        for (int i = 0; i < 2; i++)
#pragma unroll
            for (int rr = 0; rr < 2; rr++) {
                size_t r0 = (size_t)(base + m * 16 + g + 8 * rr) * 32 + colb + i * 8 + 2 * tg;
                *(float2*)&hout[r0] =
                    make_float2(h0D[m][i * 4 + rr * 2], h0D[m][i * 4 + rr * 2 + 1]);
                *(float2*)&hout[(size_t)BATCH * 32 + r0] =
                    make_float2(h1D[m][i * 4 + rr * 2], h1D[m][i * 4 + rr * 2 + 1]);
            }
#undef BARP
#undef STORE_H
#undef LOAD_A
}

extern "C" void kernel_launch(void* const* d_in, const int* in_sizes, int n_in,
                              void* d_out, int out_size) {
    (void)in_sizes; (void)n_in; (void)out_size;
    const float* x    = (const float*)d_in[0];
    const float* h    = (const float*)d_in[1];
    const float* Wih0 = (const float*)d_in[2];
    const float* Whh0 = (const float*)d_in[3];
    const float* bih0 = (const float*)d_in[4];
    const float* bhh0 = (const float*)d_in[5];
    const float* Wih1 = (const float*)d_in[6];
    const float* Whh1 = (const float*)d_in[7];
    const float* bih1 = (const float*)d_in[8];
    const float* bhh1 = (const float*)d_in[9];
    const float* Wout = (const float*)d_in[10];
    const float* bout = (const float*)d_in[11];

    // 148 blocks x 4 warps (2 pairs): 256 pair-units x 32 rows = 8192
    gru2_hmma32_kernel<<<148, 128>>>(x, h, Wih0, Whh0, bih0, bhh0,
                                     Wih1, Whh1, bih1, bhh1, Wout, bout,
                                     (float*)d_out);
}

// round 8
// speedup vs baseline: 1.1197x; 1.1197x over previous
#include <cuda_runtime.h>
#include <cstdint>

#define SEQ   256
#define BATCH 8192

// pack two f32 -> f16x2 (lo = first arg)
__device__ __forceinline__ uint32_t pkh(float lo, float hi) {
    uint32_t u; asm("cvt.rn.f16x2.f32 %0, %2, %1;" : "=r"(u) : "f"(lo), "f"(hi)); return u;
}
__device__ __forceinline__ void mma16(float d[4], const uint32_t a[4], uint32_t b0, uint32_t b1) {
    asm("mma.sync.aligned.m16n8k16.row.col.f32.f16.f16.f32 "
        "{%0,%1,%2,%3},{%4,%5,%6,%7},{%8,%9},{%0,%1,%2,%3};"
        : "+f"(d[0]), "+f"(d[1]), "+f"(d[2]), "+f"(d[3])
        : "r"(a[0]), "r"(a[1]), "r"(a[2]), "r"(a[3]), "r"(b0), "r"(b1));
}
__device__ __forceinline__ float sig_t(float x) {
    float t; asm("tanh.approx.f32 %0, %1;" : "=f"(t) : "f"(0.5f * x));
    return fmaf(t, 0.5f, 0.5f);
}
__device__ __forceinline__ float tanh_ap(float x) {
    float t; asm("tanh.approx.f32 %0, %1;" : "=f"(t) : "f"(x)); return t;
}

// Grid: 128 blocks x 512 threads (16 warps = 4 groups of 4 warps).
// Group G = blockIdx.x*4 + (wid>>2) owns rows [16G, 16G+16); all 512 active.
// Warp q = wid&3 owns hidden-unit columns [8q, 8q+8).
// Lane: g = lane>>2 (rows g, g+8), tg = lane&3 (cols 2tg, 2tg+1 in own block).
__global__ void __launch_bounds__(512, 1) gru2_hmma4_kernel(
    const float* __restrict__ x,
    const float* __restrict__ h_in,
    const float* __restrict__ Wih0,
    const float* __restrict__ Whh0,
    const float* __restrict__ bih0,
    const float* __restrict__ bhh0,
    const float* __restrict__ Wih1,
    const float* __restrict__ Whh1,
    const float* __restrict__ bih1,
    const float* __restrict__ bhh1,
    const float* __restrict__ Wout,
    const float* __restrict__ bout,
    float* __restrict__ out)
{
    // fp16 B-fragment table: per quarter q4 (cols 8q4..8q4+8), 9 uint4-slots:
    //  t=0..2 : L0 Whh0 gate t, rows t*32 + 8q4, K=32
    //  t=3,4  : L1 r : Wih1 rows 8q4 / Whh1 rows 8q4
    //  t=5,6  : L1 z : Wih1 rows 32+8q4 / Whh1 rows 32+8q4
    //  t=7    : L1 i_n: Wih1 rows 64+8q4
    //  t=8    : L1 h_n: Whh1 rows 64+8q4
    __shared__ __align__(16) uint4  BW[36 * 32];       // 18432 B
    __shared__ float4 cA4s[32];                         // (WihR,WihZ,WihN,bin0)
    __shared__ float4 cB0s[32];                         // (br0c,bz0c,bhn0,Wout)
    __shared__ float4 cB1s[32];                         // (br1c,bz1c,bin1,bhn1)
    __shared__ uint32_t hs0[4 * 16 * 20];               // f16x2 h0: 4 grp x 16 rows
    __shared__ uint32_t hs1[4 * 16 * 20];               // f16x2 h1
    __shared__ float  yS[4 * 64];                       // 4 grp x 4 q x 16 rows
    __shared__ float  boS;

    const int tid = threadIdx.x;

    for (int idx = tid; idx < 36 * 32; idx += 512) {
        int blkid = idx >> 5, l = idx & 31, gg = l >> 2, tt = l & 3;
        int q4 = blkid / 9, t = blkid - q4 * 9;
        const float* src; int rowb;
        if (t < 3)       { src = Whh0; rowb = t * 32 + 8 * q4; }
        else if (t == 3) { src = Wih1; rowb = 8 * q4; }
        else if (t == 4) { src = Whh1; rowb = 8 * q4; }
        else if (t == 5) { src = Wih1; rowb = 32 + 8 * q4; }
        else if (t == 6) { src = Whh1; rowb = 32 + 8 * q4; }
        else if (t == 7) { src = Wih1; rowb = 64 + 8 * q4; }
        else             { src = Whh1; rowb = 64 + 8 * q4; }
        const float* wr = src + (rowb + gg) * 32 + 2 * tt;
        BW[idx] = make_uint4(pkh(wr[0],  wr[1]),  pkh(wr[8],  wr[9]),
                             pkh(wr[16], wr[17]), pkh(wr[24], wr[25]));
    }
    if (tid < 32) {
        int j = tid;
        cA4s[j] = make_float4(Wih0[j], Wih0[32 + j], Wih0[64 + j], bih0[64 + j]);
        cB0s[j] = make_float4(bih0[j] + bhh0[j], bih0[32 + j] + bhh0[32 + j],
                              bhh0[64 + j], Wout[j]);
        cB1s[j] = make_float4(bih1[j] + bhh1[j], bih1[32 + j] + bhh1[32 + j],
                              bih1[64 + j], bhh1[64 + j]);
    }
    if (tid == 0) boS = bout[0];
    __syncthreads();

    const int wid  = tid >> 5;
    const int lane = tid & 31;
    const int gib  = wid >> 2;        // group in block (0..3)
    const int q    = wid & 3;         // column quarter
    const int G    = blockIdx.x * 4 + gib;

    const int g  = lane >> 2;
    const int tg = lane & 3;
    const int base = G * 16;
    const int barId = 1 + gib;
    const int colb = q * 8;
    uint32_t* hx0 = hs0 + gib * 320;
    uint32_t* hx1 = hs1 + gib * 320;
    float* yP = yS + gib * 64;
    const uint4* BWs = BW + q * 9 * 32;
    const float bo = boS;

#define BARP() asm volatile("bar.sync %0, 128;" :: "r"(barId) : "memory")

    // per-lane gate constants for owned cols (c=0,1 -> col colb+2tg+c)
    float4 cAr[2], cB0r[2], cB1r[2];
#pragma unroll
    for (int c = 0; c < 2; c++) {
        int j = colb + 2 * tg + c;
        cAr[c]  = cA4s[j];
        cB0r[c] = cB0s[j];
        cB1r[c] = cB1s[j];
    }

    // h in D-layout (fp32): idx rr*2+c, rows g+8rr, cols colb+2tg+c
    float h0D[4], h1D[4];
#pragma unroll
    for (int rr = 0; rr < 2; rr++) {
        size_t r0 = (size_t)(base + g + 8 * rr) * 32 + colb + 2 * tg;
        float2 v0 = *(const float2*)&h_in[r0];
        float2 v1 = *(const float2*)&h_in[(size_t)BATCH * 32 + r0];
        h0D[rr * 2] = v0.x; h0D[rr * 2 + 1] = v0.y;
        h1D[rr * 2] = v1.x; h1D[rr * 2 + 1] = v1.y;
    }

    uint32_t h0A[8], h1A[8];   // fp16 A fragments (full K=32), [kp*4 + slot]

    // exchange rows: 20 words; word w holds cols {2w, 2w+1}; warp q owns words 4q..4q+3
#define STORE_H(hD, hx)                                                          \
    do {                                                                         \
        _Pragma("unroll")                                                        \
        for (int rr = 0; rr < 2; rr++)                                           \
            hx[(g + 8 * rr) * 20 + 4 * q + tg] = pkh(hD[rr * 2], hD[rr * 2 + 1]); \
    } while (0)

#define LOAD_A(hx, hA)                                                           \
    do {                                                                         \
        _Pragma("unroll")                                                        \
        for (int kp = 0; kp < 2; kp++) {                                         \
            hA[kp * 4 + 0] = hx[g * 20 + tg + 8 * kp];                           \
            hA[kp * 4 + 1] = hx[(g + 8) * 20 + tg + 8 * kp];                     \
            hA[kp * 4 + 2] = hx[g * 20 + tg + 4 + 8 * kp];                       \
            hA[kp * 4 + 3] = hx[(g + 8) * 20 + tg + 4 + 8 * kp];                 \
        }                                                                        \
    } while (0)

    STORE_H(h0D, hx0);
    STORE_H(h1D, hx1);
    BARP();
    LOAD_A(hx0, h0A);
    LOAD_A(hx1, h1A);

    float xc0 = __ldg(x + base + g);
    float xc8 = __ldg(x + base + g + 8);

    for (int st = 0; st < SEQ; st++) {
        const size_t nxt = (size_t)min(st + 1, SEQ - 1) * BATCH;
        float xn0 = __ldg(x + nxt + base + g);
        float xn8 = __ldg(x + nxt + base + g + 8);

        // ---------- layer 0: 3 B-loads, 6 MMAs ----------
        float Dr[4] = {0, 0, 0, 0}, Dz[4] = {0, 0, 0, 0}, Dn[4] = {0, 0, 0, 0};
        {
            uint4 Br = BWs[0 * 32 + lane];
            uint4 Bz = BWs[1 * 32 + lane];
            uint4 Bn = BWs[2 * 32 + lane];
            mma16(Dr, h0A, Br.x, Br.y); mma16(Dr, h0A + 4, Br.z, Br.w);
            mma16(Dz, h0A, Bz.x, Bz.y); mma16(Dz, h0A + 4, Bz.z, Bz.w);
            mma16(Dn, h0A, Bn.x, Bn.y); mma16(Dn, h0A + 4, Bn.z, Bn.w);
        }
#pragma unroll
        for (int c = 0; c < 2; c++) {
            const float4 A  = cAr[c];
            const float4 Bc = cB0r[c];
#pragma unroll
            for (int rr = 0; rr < 2; rr++) {
                const float xv = rr ? xc8 : xc0;
                const int di = rr * 2 + c;
                float r = sig_t(fmaf(xv, A.x, Dr[di] + Bc.x));
                float z = sig_t(fmaf(xv, A.y, Dz[di] + Bc.y));
                float n = tanh_ap(fmaf(xv, A.z, A.w) + r * (Dn[di] + Bc.z));
                float hold = h0D[di];
                h0D[di] = n + z * (hold - n);
            }
        }
        STORE_H(h0D, hx0);
        BARP();
        LOAD_A(hx0, h0A);

        // ---------- layer 1: 6 B-loads, 12 MMAs ----------
        float Er[4] = {0, 0, 0, 0}, Ez[4] = {0, 0, 0, 0};
        float Ein[4] = {0, 0, 0, 0}, Ehn[4] = {0, 0, 0, 0};
        {
            uint4 Bri = BWs[3 * 32 + lane];
            uint4 Brh = BWs[4 * 32 + lane];
            uint4 Bzi = BWs[5 * 32 + lane];
            uint4 Bzh = BWs[6 * 32 + lane];
            uint4 Bin = BWs[7 * 32 + lane];
            uint4 Bhn = BWs[8 * 32 + lane];
            mma16(Er, h0A, Bri.x, Bri.y); mma16(Er, h0A + 4, Bri.z, Bri.w);
            mma16(Er, h1A, Brh.x, Brh.y); mma16(Er, h1A + 4, Brh.z, Brh.w);
            mma16(Ez, h0A, Bzi.x, Bzi.y); mma16(Ez, h0A + 4, Bzi.z, Bzi.w);
            mma16(Ez, h1A, Bzh.x, Bzh.y); mma16(Ez, h1A + 4, Bzh.z, Bzh.w);
            mma16(Ein, h0A, Bin.x, Bin.y); mma16(Ein, h0A + 4, Bin.z, Bin.w);
            mma16(Ehn, h1A, Bhn.x, Bhn.y); mma16(Ehn, h1A + 4, Bhn.z, Bhn.w);
        }

        float y0 = 0.0f, y1 = 0.0f;
#pragma unroll
        for (int c = 0; c < 2; c++) {
            const float4 C = cB1r[c];
            const float w = cB0r[c].w;
#pragma unroll
            for (int rr = 0; rr < 2; rr++) {
                const int di = rr * 2 + c;
                float r = sig_t(Er[di] + C.x);
                float z = sig_t(Ez[di] + C.y);
                float n = tanh_ap(Ein[di] + C.z + r * (Ehn[di] + C.w));
                float hold = h1D[di];
                float hn = n + z * (hold - n);
                h1D[di] = hn;
                if (rr) y1 = fmaf(hn, w, y1); else y0 = fmaf(hn, w, y0);
            }
        }
        STORE_H(h1D, hx1);
        y0 += __shfl_xor_sync(0xffffffffu, y0, 1);
        y0 += __shfl_xor_sync(0xffffffffu, y0, 2);
        y1 += __shfl_xor_sync(0xffffffffu, y1, 1);
        y1 += __shfl_xor_sync(0xffffffffu, y1, 2);
        if (tg == 0) {
            yP[q * 16 + g]     = y0;
            yP[q * 16 + g + 8] = y1;
        }
        BARP();
        LOAD_A(hx1, h1A);
        if (q == 0 && tg == 0) {
            out[(size_t)st * BATCH + base + g] =
                yP[g] + yP[16 + g] + yP[32 + g] + yP[48 + g] + bo;
            out[(size_t)st * BATCH + base + g + 8] =
                yP[g + 8] + yP[16 + g + 8] + yP[32 + g + 8] + yP[48 + g + 8] + bo;
        }
        xc0 = xn0;
        xc8 = xn8;
    }

    // final h_state (2, B, 32): each warp writes its own 8 columns
    float* hout = out + (size_t)SEQ * BATCH;
#pragma unroll
    for (int rr = 0; rr < 2; rr++) {
        size_t r0 = (size_t)(base + g + 8 * rr) * 32 + colb + 2 * tg;
        *(float2*)&hout[r0] = make_float2(h0D[rr * 2], h0D[rr * 2 + 1]);
        *(float2*)&hout[(size_t)BATCH * 32 + r0] = make_float2(h1D[rr * 2], h1D[rr * 2 + 1]);
    }
#undef BARP
#undef STORE_H
#undef LOAD_A
}

extern "C" void kernel_launch(void* const* d_in, const int* in_sizes, int n_in,
                              void* d_out, int out_size) {
    (void)in_sizes; (void)n_in; (void)out_size;
    const float* x    = (const float*)d_in[0];
    const float* h    = (const float*)d_in[1];
    const float* Wih0 = (const float*)d_in[2];
    const float* Whh0 = (const float*)d_in[3];
    const float* bih0 = (const float*)d_in[4];
    const float* bhh0 = (const float*)d_in[5];
    const float* Wih1 = (const float*)d_in[6];
    const float* Whh1 = (const float*)d_in[7];
    const float* bih1 = (const float*)d_in[8];
    const float* bhh1 = (const float*)d_in[9];
    const float* Wout = (const float*)d_in[10];
    const float* bout = (const float*)d_in[11];

    // 128 blocks x 16 warps (4 groups): 512 groups x 16 rows = 8192, uniform
    gru2_hmma4_kernel<<<128, 512>>>(x, h, Wih0, Whh0, bih0, bhh0,
                                    Wih1, Whh1, bih1, bhh1, Wout, bout,
                                    (float*)d_out);
}